// round 3
// baseline (speedup 1.0000x reference)
#include <cuda_runtime.h>
#include <cuda_bf16.h>

// Problem constants
#define TT   4096
#define HH   16
#define DKK  128
#define QKVC 6144
#define NELEM (TT * HH * DKK)   // 8388608

// Scratch (static __device__ globals — no runtime allocation)
__device__ float g_KA[NELEM];   // k * a
__device__ float g_A [NELEM];   // a = exp(g)
__device__ float g_K [NELEM];   // l2-normed k
__device__ float g_Q [NELEM];   // l2-normed q * DK^-0.5
__device__ float g_V [NELEM];   // conv+silu v
__device__ float g_B [TT * HH]; // sigmoid(beta)

// --------------------------------------------------------------------------
// Kernel 1: conv1d(K=4, depthwise, causal) + SiLU + l2norm + gate precompute
// One warp per (t, h); lane handles 4 consecutive d via float4.
// --------------------------------------------------------------------------
__device__ __forceinline__ void conv_silu4(const float* __restrict__ x,
                                           const float* __restrict__ w,
                                           int t, int c, float out[4]) {
    float wz[4][4];
#pragma unroll
    for (int j = 0; j < 4; j++) {
        float4 wv = *(const float4*)(w + (size_t)(c + j) * 4);
        wz[j][0] = wv.x; wz[j][1] = wv.y; wz[j][2] = wv.z; wz[j][3] = wv.w;
    }
    float acc[4] = {0.f, 0.f, 0.f, 0.f};
#pragma unroll
    for (int tau = 0; tau < 4; tau++) {
        int tt = t - 3 + tau;
        if (tt >= 0) {
            float4 xv = *(const float4*)(x + (size_t)tt * QKVC + c);
            acc[0] = fmaf(xv.x, wz[0][tau], acc[0]);
            acc[1] = fmaf(xv.y, wz[1][tau], acc[1]);
            acc[2] = fmaf(xv.z, wz[2][tau], acc[2]);
            acc[3] = fmaf(xv.w, wz[3][tau], acc[3]);
        }
    }
#pragma unroll
    for (int j = 0; j < 4; j++)
        out[j] = acc[j] / (1.f + expf(-acc[j]));   // SiLU
}

__global__ void prep_kernel(const float* __restrict__ qkv,
                            const float* __restrict__ fg,
                            const float* __restrict__ beta,
                            const float* __restrict__ w,
                            const float* __restrict__ A_log,
                            const float* __restrict__ dt_bias) {
    int gw   = (blockIdx.x * blockDim.x + threadIdx.x) >> 5;
    int lane = threadIdx.x & 31;
    if (gw >= TT * HH) return;
    int t = gw >> 4;
    int h = gw & 15;
    int d = lane * 4;
    int cq = h * DKK + d;

    float qy[4], ky[4], vy[4];
    conv_silu4(qkv, w, t, cq,        qy);
    conv_silu4(qkv, w, t, cq + 2048, ky);
    conv_silu4(qkv, w, t, cq + 4096, vy);

    // l2norm sums
    float sq = 0.f, sk = 0.f;
#pragma unroll
    for (int j = 0; j < 4; j++) {
        sq = fmaf(qy[j], qy[j], sq);
        sk = fmaf(ky[j], ky[j], sk);
    }
#pragma unroll
    for (int m = 16; m > 0; m >>= 1) {
        sq += __shfl_xor_sync(0xffffffffu, sq, m);
        sk += __shfl_xor_sync(0xffffffffu, sk, m);
    }
    float se_q = sq + 1e-6f, se_k = sk + 1e-6f;
    float rq = rsqrtf(se_q); rq = rq * (1.5f - 0.5f * se_q * rq * rq);  // Newton
    float rk = rsqrtf(se_k); rk = rk * (1.5f - 0.5f * se_k * rk * rk);
    rq *= 0.08838834764831845f;   // DK^-0.5

    // gate
    float ea = expf(A_log[h]);
    float4 fgv = *(const float4*)(fg + (size_t)t * (HH * DKK) + h * DKK + d);
    float4 dbv = *(const float4*)(dt_bias + h * DKK + d);
    float zf[4] = {fgv.x + dbv.x, fgv.y + dbv.y, fgv.z + dbv.z, fgv.w + dbv.w};

    float qn[4], kn[4], av[4], kav[4];
#pragma unroll
    for (int j = 0; j < 4; j++) {
        float z  = zf[j];
        float sp = (z > 20.f) ? z : log1pf(expf(z));   // softplus
        av[j]  = expf(-ea * sp);                       // a = exp(g)
        qn[j]  = qy[j] * rq;
        kn[j]  = ky[j] * rk;
        kav[j] = kn[j] * av[j];
    }

    size_t idx = ((size_t)t * HH + h) * DKK + d;
    *(float4*)(g_Q  + idx) = make_float4(qn[0],  qn[1],  qn[2],  qn[3]);
    *(float4*)(g_K  + idx) = make_float4(kn[0],  kn[1],  kn[2],  kn[3]);
    *(float4*)(g_A  + idx) = make_float4(av[0],  av[1],  av[2],  av[3]);
    *(float4*)(g_KA + idx) = make_float4(kav[0], kav[1], kav[2], kav[3]);
    *(float4*)(g_V  + idx) = make_float4(vy[0],  vy[1],  vy[2],  vy[3]);
    if (lane == 0)
        g_B[t * HH + h] = 1.f / (1.f + expf(-beta[t * HH + h]));
}

// --------------------------------------------------------------------------
// Kernel 2: gated delta-rule recurrence. One warp per (head, v-column).
// S[:, v] lives in registers: 4 floats per lane (k = lane*4 .. lane*4+3).
// Output reduction of step t is interleaved with pred reduction of step t+1.
// --------------------------------------------------------------------------
__global__ void __launch_bounds__(512, 1)
recur_kernel(float* __restrict__ out) {
    const int warp = threadIdx.x >> 5;
    const int lane = threadIdx.x & 31;
    const int h    = blockIdx.x >> 3;                 // 16 heads, 8 CTAs each
    const int v    = ((blockIdx.x & 7) << 4) | warp;  // 0..127
    const int stride = HH * DKK;                      // 2048

    const float* pKA = g_KA + h * DKK + lane * 4;
    const float* pA  = g_A  + h * DKK + lane * 4;
    const float* pK  = g_K  + h * DKK + lane * 4;
    const float* pQ  = g_Q  + h * DKK + lane * 4;
    const float* pV  = g_V  + h * DKK + v;
    const float* pB  = g_B  + h;
    float*       pO  = out  + h * DKK + v;

    float S0 = 0.f, S1 = 0.f, S2 = 0.f, S3 = 0.f;

    // prefetch t = 0
    float4 nka = *(const float4*)pKA;
    float4 na  = *(const float4*)pA;
    float4 nk  = *(const float4*)pK;
    float4 nq  = *(const float4*)pQ;
    float  nv  = *pV;
    float  nb  = *pB;
    float  o_part = 0.f;

    for (int t = 0; t < TT; t++) {
        float4 ka = nka, aa = na, kk = nk, qq = nq;
        float  vv = nv,  bb = nb;

        // prefetch t+1 (clamped) — hidden under the reduction chain
        int    tn  = (t + 1 < TT) ? (t + 1) : (TT - 1);
        size_t off = (size_t)tn * stride;
        nka = *(const float4*)(pKA + off);
        na  = *(const float4*)(pA  + off);
        nk  = *(const float4*)(pK  + off);
        nq  = *(const float4*)(pQ  + off);
        nv  = pV[off];
        nb  = pB[(size_t)tn * HH];

        // pred partial: sum_k (k*a)[k] * S_old[k, v]
        float r1 = fmaf(ka.x, S0, ka.y * S1) + fmaf(ka.z, S2, ka.w * S3);
        float r2 = o_part;   // deferred output of step t-1
#pragma unroll
        for (int m = 16; m > 0; m >>= 1) {
            r1 += __shfl_xor_sync(0xffffffffu, r1, m);
            r2 += __shfl_xor_sync(0xffffffffu, r2, m);
        }
        if (t && lane == 0) pO[(size_t)(t - 1) * stride] = r2;

        float delta = bb * (vv - r1);
        // S_new = a[k]*S_old + k[k]*delta
        S0 = fmaf(aa.x, S0, kk.x * delta);
        S1 = fmaf(aa.y, S1, kk.y * delta);
        S2 = fmaf(aa.z, S2, kk.z * delta);
        S3 = fmaf(aa.w, S3, kk.w * delta);
        // o partial: sum_k q[k] * S_new[k, v]  (reduced next iteration)
        o_part = fmaf(qq.x, S0, qq.y * S1) + fmaf(qq.z, S2, qq.w * S3);
    }
#pragma unroll
    for (int m = 16; m > 0; m >>= 1)
        o_part += __shfl_xor_sync(0xffffffffu, o_part, m);
    if (lane == 0) pO[(size_t)(TT - 1) * stride] = o_part;
}

// --------------------------------------------------------------------------
extern "C" void kernel_launch(void* const* d_in, const int* in_sizes, int n_in,
                              void* d_out, int out_size) {
    const float* mixed_qkv   = (const float*)d_in[0];
    const float* forget_gate = (const float*)d_in[1];
    const float* beta        = (const float*)d_in[2];
    const float* conv_w      = (const float*)d_in[3];
    const float* A_log       = (const float*)d_in[4];
    const float* dt_bias     = (const float*)d_in[5];
    float* out = (float*)d_out;

    // 65536 (t,h) warps, 8 per 256-thread block
    prep_kernel<<<(TT * HH) / 8, 256>>>(mixed_qkv, forget_gate, beta,
                                        conv_w, A_log, dt_bias);
    // 2048 columns, 16 warps (columns) per block
    recur_kernel<<<128, 512>>>(out);
}

// round 4
// speedup vs baseline: 1.0028x; 1.0028x over previous
#include <cuda_runtime.h>
#include <cuda_bf16.h>

// Problem constants
#define TT   4096
#define HH   16
#define DKK  128
#define QKVC 6144
#define NELEM (TT * HH * DKK)   // 8388608

// Scratch (static __device__ globals — no runtime allocation)
__device__ float g_KA[NELEM];   // k * a
__device__ float g_A [NELEM];   // a = exp(g)
__device__ float g_K [NELEM];   // l2-normed k
__device__ float g_Q [NELEM];   // l2-normed q * DK^-0.5
__device__ float g_V [NELEM];   // conv+silu v
__device__ float g_B [TT * HH]; // sigmoid(beta)

// --------------------------------------------------------------------------
// Kernel 1: conv1d(K=4, depthwise, causal) + SiLU + l2norm + gate precompute
// One warp per (t, h); lane handles 4 consecutive d via float4.
// --------------------------------------------------------------------------
__device__ __forceinline__ void conv_silu4(const float* __restrict__ x,
                                           const float* __restrict__ w,
                                           int t, int c, float out[4]) {
    float wz[4][4];
#pragma unroll
    for (int j = 0; j < 4; j++) {
        float4 wv = *(const float4*)(w + (size_t)(c + j) * 4);
        wz[j][0] = wv.x; wz[j][1] = wv.y; wz[j][2] = wv.z; wz[j][3] = wv.w;
    }
    float acc[4] = {0.f, 0.f, 0.f, 0.f};
#pragma unroll
    for (int tau = 0; tau < 4; tau++) {
        int tt = t - 3 + tau;
        if (tt >= 0) {
            float4 xv = *(const float4*)(x + (size_t)tt * QKVC + c);
            acc[0] = fmaf(xv.x, wz[0][tau], acc[0]);
            acc[1] = fmaf(xv.y, wz[1][tau], acc[1]);
            acc[2] = fmaf(xv.z, wz[2][tau], acc[2]);
            acc[3] = fmaf(xv.w, wz[3][tau], acc[3]);
        }
    }
#pragma unroll
    for (int j = 0; j < 4; j++)
        out[j] = acc[j] / (1.f + expf(-acc[j]));   // SiLU
}

__global__ void prep_kernel(const float* __restrict__ qkv,
                            const float* __restrict__ fg,
                            const float* __restrict__ beta,
                            const float* __restrict__ w,
                            const float* __restrict__ A_log,
                            const float* __restrict__ dt_bias) {
    int gw   = (blockIdx.x * blockDim.x + threadIdx.x) >> 5;
    int lane = threadIdx.x & 31;
    if (gw >= TT * HH) return;
    int t = gw >> 4;
    int h = gw & 15;
    int d = lane * 4;
    int cq = h * DKK + d;

    float qy[4], ky[4], vy[4];
    conv_silu4(qkv, w, t, cq,        qy);
    conv_silu4(qkv, w, t, cq + 2048, ky);
    conv_silu4(qkv, w, t, cq + 4096, vy);

    // l2norm sums
    float sq = 0.f, sk = 0.f;
#pragma unroll
    for (int j = 0; j < 4; j++) {
        sq = fmaf(qy[j], qy[j], sq);
        sk = fmaf(ky[j], ky[j], sk);
    }
#pragma unroll
    for (int m = 16; m > 0; m >>= 1) {
        sq += __shfl_xor_sync(0xffffffffu, sq, m);
        sk += __shfl_xor_sync(0xffffffffu, sk, m);
    }
    float se_q = sq + 1e-6f, se_k = sk + 1e-6f;
    float rq = rsqrtf(se_q); rq = rq * (1.5f - 0.5f * se_q * rq * rq);  // Newton
    float rk = rsqrtf(se_k); rk = rk * (1.5f - 0.5f * se_k * rk * rk);
    rq *= 0.08838834764831845f;   // DK^-0.5

    // gate
    float ea = expf(A_log[h]);
    float4 fgv = *(const float4*)(fg + (size_t)t * (HH * DKK) + h * DKK + d);
    float4 dbv = *(const float4*)(dt_bias + h * DKK + d);
    float zf[4] = {fgv.x + dbv.x, fgv.y + dbv.y, fgv.z + dbv.z, fgv.w + dbv.w};

    float qn[4], kn[4], av[4], kav[4];
#pragma unroll
    for (int j = 0; j < 4; j++) {
        float z  = zf[j];
        float sp = (z > 20.f) ? z : log1pf(expf(z));   // softplus
        av[j]  = expf(-ea * sp);                       // a = exp(g)
        qn[j]  = qy[j] * rq;
        kn[j]  = ky[j] * rk;
        kav[j] = kn[j] * av[j];
    }

    size_t idx = ((size_t)t * HH + h) * DKK + d;
    *(float4*)(g_Q  + idx) = make_float4(qn[0],  qn[1],  qn[2],  qn[3]);
    *(float4*)(g_K  + idx) = make_float4(kn[0],  kn[1],  kn[2],  kn[3]);
    *(float4*)(g_A  + idx) = make_float4(av[0],  av[1],  av[2],  av[3]);
    *(float4*)(g_KA + idx) = make_float4(kav[0], kav[1], kav[2], kav[3]);
    *(float4*)(g_V  + idx) = make_float4(vy[0],  vy[1],  vy[2],  vy[3]);
    if (lane == 0)
        g_B[t * HH + h] = 1.f / (1.f + expf(-beta[t * HH + h]));
}

// --------------------------------------------------------------------------
// Kernel 2: gated delta-rule recurrence. One warp per (head, v-column).
// S[:, v] lives in registers: 4 floats per lane (k = lane*4 .. lane*4+3).
// Output reduction of step t is interleaved with pred reduction of step t+1.
// --------------------------------------------------------------------------
__global__ void __launch_bounds__(512, 1)
recur_kernel(float* __restrict__ out) {
    const int warp = threadIdx.x >> 5;
    const int lane = threadIdx.x & 31;
    const int h    = blockIdx.x >> 3;                 // 16 heads, 8 CTAs each
    const int v    = ((blockIdx.x & 7) << 4) | warp;  // 0..127
    const int stride = HH * DKK;                      // 2048

    const float* pKA = g_KA + h * DKK + lane * 4;
    const float* pA  = g_A  + h * DKK + lane * 4;
    const float* pK  = g_K  + h * DKK + lane * 4;
    const float* pQ  = g_Q  + h * DKK + lane * 4;
    const float* pV  = g_V  + h * DKK + v;
    const float* pB  = g_B  + h;
    float*       pO  = out  + h * DKK + v;

    float S0 = 0.f, S1 = 0.f, S2 = 0.f, S3 = 0.f;

    // prefetch t = 0
    float4 nka = *(const float4*)pKA;
    float4 na  = *(const float4*)pA;
    float4 nk  = *(const float4*)pK;
    float4 nq  = *(const float4*)pQ;
    float  nv  = *pV;
    float  nb  = *pB;
    float  o_part = 0.f;

    for (int t = 0; t < TT; t++) {
        float4 ka = nka, aa = na, kk = nk, qq = nq;
        float  vv = nv,  bb = nb;

        // prefetch t+1 (clamped) — hidden under the reduction chain
        int    tn  = (t + 1 < TT) ? (t + 1) : (TT - 1);
        size_t off = (size_t)tn * stride;
        nka = *(const float4*)(pKA + off);
        na  = *(const float4*)(pA  + off);
        nk  = *(const float4*)(pK  + off);
        nq  = *(const float4*)(pQ  + off);
        nv  = pV[off];
        nb  = pB[(size_t)tn * HH];

        // pred partial: sum_k (k*a)[k] * S_old[k, v]
        float r1 = fmaf(ka.x, S0, ka.y * S1) + fmaf(ka.z, S2, ka.w * S3);
        float r2 = o_part;   // deferred output of step t-1
#pragma unroll
        for (int m = 16; m > 0; m >>= 1) {
            r1 += __shfl_xor_sync(0xffffffffu, r1, m);
            r2 += __shfl_xor_sync(0xffffffffu, r2, m);
        }
        if (t && lane == 0) pO[(size_t)(t - 1) * stride] = r2;

        float delta = bb * (vv - r1);
        // S_new = a[k]*S_old + k[k]*delta
        S0 = fmaf(aa.x, S0, kk.x * delta);
        S1 = fmaf(aa.y, S1, kk.y * delta);
        S2 = fmaf(aa.z, S2, kk.z * delta);
        S3 = fmaf(aa.w, S3, kk.w * delta);
        // o partial: sum_k q[k] * S_new[k, v]  (reduced next iteration)
        o_part = fmaf(qq.x, S0, qq.y * S1) + fmaf(qq.z, S2, qq.w * S3);
    }
#pragma unroll
    for (int m = 16; m > 0; m >>= 1)
        o_part += __shfl_xor_sync(0xffffffffu, o_part, m);
    if (lane == 0) pO[(size_t)(TT - 1) * stride] = o_part;
}

// --------------------------------------------------------------------------
extern "C" void kernel_launch(void* const* d_in, const int* in_sizes, int n_in,
                              void* d_out, int out_size) {
    const float* mixed_qkv   = (const float*)d_in[0];
    const float* forget_gate = (const float*)d_in[1];
    const float* beta        = (const float*)d_in[2];
    const float* conv_w      = (const float*)d_in[3];
    const float* A_log       = (const float*)d_in[4];
    const float* dt_bias     = (const float*)d_in[5];
    float* out = (float*)d_out;

    // 65536 (t,h) warps, 8 per 256-thread block
    prep_kernel<<<(TT * HH) / 8, 256>>>(mixed_qkv, forget_gate, beta,
                                        conv_w, A_log, dt_bias);
    // 2048 columns, 16 warps (columns) per block
    recur_kernel<<<128, 512>>>(out);
}

// round 5
// speedup vs baseline: 2.1810x; 2.1750x over previous
#include <cuda_runtime.h>
#include <cuda_bf16.h>

// Problem constants
#define TT   4096
#define HH   16
#define DKK  128
#define QKVC 6144
#define NELEM (TT * HH * DKK)   // 8388608

// Scratch (static __device__ globals — no runtime allocation)
// g_P: packed per (t,h): [ka(128) | a(128) | k(128) | q(128)]  (2KB block)
__device__ float g_P[TT * HH * 512];
__device__ float g_V[NELEM];    // conv+silu v
__device__ float g_B[TT * HH];  // sigmoid(beta)

// --------------------------------------------------------------------------
// f32x2 packed-math helpers (FFMA2 path; ptxas only emits via PTX f32x2)
// --------------------------------------------------------------------------
__device__ __forceinline__ unsigned long long ffma2(unsigned long long a,
                                                    unsigned long long b,
                                                    unsigned long long c) {
    unsigned long long d;
    asm("fma.rn.f32x2 %0, %1, %2, %3;" : "=l"(d) : "l"(a), "l"(b), "l"(c));
    return d;
}
__device__ __forceinline__ unsigned long long fmul2(unsigned long long a,
                                                    unsigned long long b) {
    unsigned long long d;
    asm("mul.rn.f32x2 %0, %1, %2;" : "=l"(d) : "l"(a), "l"(b));
    return d;
}
__device__ __forceinline__ unsigned long long fadd2(unsigned long long a,
                                                    unsigned long long b) {
    unsigned long long d;
    asm("add.rn.f32x2 %0, %1, %2;" : "=l"(d) : "l"(a), "l"(b));
    return d;
}
__device__ __forceinline__ float hsum2(unsigned long long a) {
    float lo, hi;
    asm("mov.b64 {%0, %1}, %2;" : "=f"(lo), "=f"(hi) : "l"(a));
    return lo + hi;
}
__device__ __forceinline__ unsigned long long pack2(float x) {
    unsigned long long d;
    asm("mov.b64 %0, {%1, %1};" : "=l"(d) : "f"(x));
    return d;
}

// cp.async helpers
__device__ __forceinline__ void cp16(float* dst, const float* src) {
    unsigned d = (unsigned)__cvta_generic_to_shared(dst);
    asm volatile("cp.async.cg.shared.global [%0], [%1], 16;"
                 :: "r"(d), "l"(src) : "memory");
}
__device__ __forceinline__ void cp4(float* dst, const float* src) {
    unsigned d = (unsigned)__cvta_generic_to_shared(dst);
    asm volatile("cp.async.ca.shared.global [%0], [%1], 4;"
                 :: "r"(d), "l"(src) : "memory");
}

// --------------------------------------------------------------------------
// Kernel 1: conv1d(K=4, depthwise, causal) + SiLU + l2norm + gate precompute
// One warp per (t, h); lane handles 4 consecutive d via float4.
// --------------------------------------------------------------------------
__device__ __forceinline__ void conv_silu4(const float* __restrict__ x,
                                           const float* __restrict__ w,
                                           int t, int c, float out[4]) {
    float wz[4][4];
#pragma unroll
    for (int j = 0; j < 4; j++) {
        float4 wv = *(const float4*)(w + (size_t)(c + j) * 4);
        wz[j][0] = wv.x; wz[j][1] = wv.y; wz[j][2] = wv.z; wz[j][3] = wv.w;
    }
    float acc[4] = {0.f, 0.f, 0.f, 0.f};
#pragma unroll
    for (int tau = 0; tau < 4; tau++) {
        int tt = t - 3 + tau;
        if (tt >= 0) {
            float4 xv = *(const float4*)(x + (size_t)tt * QKVC + c);
            acc[0] = fmaf(xv.x, wz[0][tau], acc[0]);
            acc[1] = fmaf(xv.y, wz[1][tau], acc[1]);
            acc[2] = fmaf(xv.z, wz[2][tau], acc[2]);
            acc[3] = fmaf(xv.w, wz[3][tau], acc[3]);
        }
    }
#pragma unroll
    for (int j = 0; j < 4; j++)
        out[j] = acc[j] / (1.f + expf(-acc[j]));   // SiLU
}

__global__ void prep_kernel(const float* __restrict__ qkv,
                            const float* __restrict__ fg,
                            const float* __restrict__ beta,
                            const float* __restrict__ w,
                            const float* __restrict__ A_log,
                            const float* __restrict__ dt_bias) {
    int gw   = (blockIdx.x * blockDim.x + threadIdx.x) >> 5;
    int lane = threadIdx.x & 31;
    if (gw >= TT * HH) return;
    int t = gw >> 4;
    int h = gw & 15;
    int d = lane * 4;
    int cq = h * DKK + d;

    float qy[4], ky[4], vy[4];
    conv_silu4(qkv, w, t, cq,        qy);
    conv_silu4(qkv, w, t, cq + 2048, ky);
    conv_silu4(qkv, w, t, cq + 4096, vy);

    // l2norm sums
    float sq = 0.f, sk = 0.f;
#pragma unroll
    for (int j = 0; j < 4; j++) {
        sq = fmaf(qy[j], qy[j], sq);
        sk = fmaf(ky[j], ky[j], sk);
    }
#pragma unroll
    for (int m = 16; m > 0; m >>= 1) {
        sq += __shfl_xor_sync(0xffffffffu, sq, m);
        sk += __shfl_xor_sync(0xffffffffu, sk, m);
    }
    float se_q = sq + 1e-6f, se_k = sk + 1e-6f;
    float rq = rsqrtf(se_q); rq = rq * (1.5f - 0.5f * se_q * rq * rq);  // Newton
    float rk = rsqrtf(se_k); rk = rk * (1.5f - 0.5f * se_k * rk * rk);
    rq *= 0.08838834764831845f;   // DK^-0.5

    // gate
    float ea = expf(A_log[h]);
    float4 fgv = *(const float4*)(fg + (size_t)t * (HH * DKK) + h * DKK + d);
    float4 dbv = *(const float4*)(dt_bias + h * DKK + d);
    float zf[4] = {fgv.x + dbv.x, fgv.y + dbv.y, fgv.z + dbv.z, fgv.w + dbv.w};

    float qn[4], kn[4], av[4], kav[4];
#pragma unroll
    for (int j = 0; j < 4; j++) {
        float z  = zf[j];
        float sp = (z > 20.f) ? z : log1pf(expf(z));   // softplus
        av[j]  = expf(-ea * sp);                       // a = exp(g)
        qn[j]  = qy[j] * rq;
        kn[j]  = ky[j] * rk;
        kav[j] = kn[j] * av[j];
    }

    size_t pb = ((size_t)t * HH + h) * 512 + d;
    *(float4*)(g_P + pb      ) = make_float4(kav[0], kav[1], kav[2], kav[3]);
    *(float4*)(g_P + pb + 128) = make_float4(av[0],  av[1],  av[2],  av[3]);
    *(float4*)(g_P + pb + 256) = make_float4(kn[0],  kn[1],  kn[2],  kn[3]);
    *(float4*)(g_P + pb + 384) = make_float4(qn[0],  qn[1],  qn[2],  qn[3]);
    *(float4*)(g_V + ((size_t)t * HH + h) * DKK + d) =
        make_float4(vy[0], vy[1], vy[2], vy[3]);
    if (lane == 0)
        g_B[t * HH + h] = 1.f / (1.f + expf(-beta[t * HH + h]));
}

// --------------------------------------------------------------------------
// Kernel 2: gated delta-rule recurrence.
// One warp handles 4 v-columns; lane = cg*8 + kg, cg in [0,4) = column group,
// kg in [0,8) = k group. Lane's k-slice: k in { j*32 + kg*4 + (0..3), j=0..3 }
// (16 values = 8 f32x2 pairs). Reduction over kg = 3 butterfly levels.
// Per-step data staged via cp.async into smem (2-step groups, 3 in flight).
// --------------------------------------------------------------------------
#define STGF 544   // floats per stage: 512 packed + 16 v + 1 b + pad
#define NSTG 8     // 4 groups x 2 steps

__global__ void __launch_bounds__(128, 1)
recur_kernel(float* __restrict__ out) {
    __shared__ __align__(16) float sm[NSTG * STGF];

    const int tid  = threadIdx.x;
    const int warp = tid >> 5;
    const int lane = tid & 31;
    const int kg   = lane & 7;
    const int cg   = lane >> 3;
    const int h    = blockIdx.x >> 3;
    const int vb   = (blockIdx.x & 7) * 16;       // CTA's 16-column slab
    const int vcol = vb + warp * 4 + cg;          // this lane's column
    float* outp = out + h * DKK + vcol;

    auto issue = [&](int g) {
#pragma unroll
        for (int s = 0; s < 2; s++) {
            int t = 2 * g + s; if (t > TT - 1) t = TT - 1;
            float* sp = sm + ((g & 3) * 2 + s) * STGF;
            const float* gp = g_P + ((size_t)t * HH + h) * 512;
            cp16(sp + tid * 4, gp + tid * 4);
            if (tid < 4)
                cp16(sp + 512 + tid * 4,
                     g_V + ((size_t)t * HH + h) * DKK + vb + tid * 4);
            if (tid == 4)
                cp4(sp + 528, g_B + t * HH + h);
        }
        asm volatile("cp.async.commit_group;" ::: "memory");
    };

    issue(0); issue(1); issue(2);

    unsigned long long S[8] = {0, 0, 0, 0, 0, 0, 0, 0};
    float o_part = 0.f;

    for (int g = 0; g < TT / 2; g++) {
        asm volatile("cp.async.wait_group 2;" ::: "memory");
        __syncthreads();
#pragma unroll
        for (int s = 0; s < 2; s++) {
            const int t = 2 * g + s;
            const float* spb = sm + ((g & 3) * 2 + s) * STGF;
            const float* sp  = spb + kg * 4;

            // stage loads (conflict-free LDS.128, 4-way broadcast)
            ulonglong2 KA[4], AA[4], KK[4], QQ[4];
#pragma unroll
            for (int j = 0; j < 4; j++) {
                KA[j] = *(const ulonglong2*)(sp +   0 + j * 32);
                AA[j] = *(const ulonglong2*)(sp + 128 + j * 32);
                KK[j] = *(const ulonglong2*)(sp + 256 + j * 32);
                QQ[j] = *(const ulonglong2*)(sp + 384 + j * 32);
            }
            float vv = spb[512 + warp * 4 + cg];
            float bb = spb[528];

            // pred partial: sum_k (k*a)[k] * S_old[k, vcol]   (f32x2)
            unsigned long long a0 = 0ull, a1 = 0ull;
            a0 = ffma2(KA[0].x, S[0], a0); a1 = ffma2(KA[0].y, S[1], a1);
            a0 = ffma2(KA[1].x, S[2], a0); a1 = ffma2(KA[1].y, S[3], a1);
            a0 = ffma2(KA[2].x, S[4], a0); a1 = ffma2(KA[2].y, S[5], a1);
            a0 = ffma2(KA[3].x, S[6], a0); a1 = ffma2(KA[3].y, S[7], a1);
            float r1 = hsum2(fadd2(a0, a1));
            float r2 = o_part;   // deferred output of step t-1

            // 3-level butterfly over kg; two interleaved chains
#pragma unroll
            for (int m = 1; m < 8; m <<= 1) {
                r1 += __shfl_xor_sync(0xffffffffu, r1, m);
                r2 += __shfl_xor_sync(0xffffffffu, r2, m);
            }
            if (t && kg == 0) outp[(size_t)(t - 1) * (HH * DKK)] = r2;

            float dlt = bb * (vv - r1);
            unsigned long long D2 = pack2(dlt);

            // S = a*S + k*delta ; out partial = q . S_new
            unsigned long long o0 = 0ull, o1 = 0ull;
#pragma unroll
            for (int j = 0; j < 4; j++) {
                S[2*j]   = ffma2(AA[j].x, S[2*j],   fmul2(KK[j].x, D2));
                S[2*j+1] = ffma2(AA[j].y, S[2*j+1], fmul2(KK[j].y, D2));
                o0 = ffma2(QQ[j].x, S[2*j],   o0);
                o1 = ffma2(QQ[j].y, S[2*j+1], o1);
            }
            o_part = hsum2(fadd2(o0, o1));
        }
        issue(g + 3);
    }

    // flush last step's output
#pragma unroll
    for (int m = 1; m < 8; m <<= 1)
        o_part += __shfl_xor_sync(0xffffffffu, o_part, m);
    if (kg == 0) outp[(size_t)(TT - 1) * (HH * DKK)] = o_part;
}

// --------------------------------------------------------------------------
extern "C" void kernel_launch(void* const* d_in, const int* in_sizes, int n_in,
                              void* d_out, int out_size) {
    const float* mixed_qkv   = (const float*)d_in[0];
    const float* forget_gate = (const float*)d_in[1];
    const float* beta        = (const float*)d_in[2];
    const float* conv_w      = (const float*)d_in[3];
    const float* A_log       = (const float*)d_in[4];
    const float* dt_bias     = (const float*)d_in[5];
    float* out = (float*)d_out;

    // 65536 (t,h) warps, 8 per 256-thread block
    prep_kernel<<<(TT * HH) / 8, 256>>>(mixed_qkv, forget_gate, beta,
                                        conv_w, A_log, dt_bias);
    // 2048 columns / 4 per warp = 512 warps -> 128 CTAs x 128 threads
    recur_kernel<<<128, 128>>>(out);
}

// round 6
// speedup vs baseline: 2.2766x; 1.0438x over previous
#include <cuda_runtime.h>
#include <cuda_bf16.h>

// Problem constants
#define TT   4096
#define HH   16
#define DKK  128
#define QKVC 6144
#define NELEM (TT * HH * DKK)   // 8388608

// Scratch (static __device__ globals — no runtime allocation)
// g_P packed per (t,h): [slot0(128) | a(128) | k(128) | q(128)]
// slot0 holds ka after prep; pass2 overwrites it in place with
// w_t = ka_t ∘ a_{t-1} ∘ a_{t-2} (only warp (t,h) ever touches slot0 of (t,h)).
__device__ __align__(16) float g_P [TT * HH * 512];
__device__ __align__(16) float g_BV[NELEM];        // b * (conv+silu v)
__device__ __align__(16) float g_S4[TT * HH * 4];  // {b, R, Q, 0} per (t,h)
__device__ float g_B[TT * HH];                     // sigmoid(beta)

// --------------------------------------------------------------------------
// f32x2 packed-math helpers (FFMA2 path; ptxas only emits via PTX f32x2)
// --------------------------------------------------------------------------
__device__ __forceinline__ unsigned long long ffma2(unsigned long long a,
                                                    unsigned long long b,
                                                    unsigned long long c) {
    unsigned long long d;
    asm("fma.rn.f32x2 %0, %1, %2, %3;" : "=l"(d) : "l"(a), "l"(b), "l"(c));
    return d;
}
__device__ __forceinline__ unsigned long long fmul2(unsigned long long a,
                                                    unsigned long long b) {
    unsigned long long d;
    asm("mul.rn.f32x2 %0, %1, %2;" : "=l"(d) : "l"(a), "l"(b));
    return d;
}
__device__ __forceinline__ unsigned long long fadd2(unsigned long long a,
                                                    unsigned long long b) {
    unsigned long long d;
    asm("add.rn.f32x2 %0, %1, %2;" : "=l"(d) : "l"(a), "l"(b));
    return d;
}
__device__ __forceinline__ float hsum2(unsigned long long a) {
    float lo, hi;
    asm("mov.b64 {%0, %1}, %2;" : "=f"(lo), "=f"(hi) : "l"(a));
    return lo + hi;
}
__device__ __forceinline__ unsigned long long pack2(float x) {
    unsigned long long d;
    asm("mov.b64 %0, {%1, %1};" : "=l"(d) : "f"(x));
    return d;
}

// cp.async helper
__device__ __forceinline__ void cp16(float* dst, const float* src) {
    unsigned d = (unsigned)__cvta_generic_to_shared(dst);
    asm volatile("cp.async.cg.shared.global [%0], [%1], 16;"
                 :: "r"(d), "l"(src) : "memory");
}

// --------------------------------------------------------------------------
// Kernel 1: conv1d(K=4, depthwise, causal) + SiLU + l2norm + gate precompute
// One warp per (t, h); lane handles 4 consecutive d via float4.
// --------------------------------------------------------------------------
__device__ __forceinline__ void conv_silu4(const float* __restrict__ x,
                                           const float* __restrict__ w,
                                           int t, int c, float out[4]) {
    float wz[4][4];
#pragma unroll
    for (int j = 0; j < 4; j++) {
        float4 wv = *(const float4*)(w + (size_t)(c + j) * 4);
        wz[j][0] = wv.x; wz[j][1] = wv.y; wz[j][2] = wv.z; wz[j][3] = wv.w;
    }
    float acc[4] = {0.f, 0.f, 0.f, 0.f};
#pragma unroll
    for (int tau = 0; tau < 4; tau++) {
        int tt = t - 3 + tau;
        if (tt >= 0) {
            float4 xv = *(const float4*)(x + (size_t)tt * QKVC + c);
            acc[0] = fmaf(xv.x, wz[0][tau], acc[0]);
            acc[1] = fmaf(xv.y, wz[1][tau], acc[1]);
            acc[2] = fmaf(xv.z, wz[2][tau], acc[2]);
            acc[3] = fmaf(xv.w, wz[3][tau], acc[3]);
        }
    }
#pragma unroll
    for (int j = 0; j < 4; j++)
        out[j] = acc[j] / (1.f + expf(-acc[j]));   // SiLU
}

__global__ void prep_kernel(const float* __restrict__ qkv,
                            const float* __restrict__ fg,
                            const float* __restrict__ beta,
                            const float* __restrict__ w,
                            const float* __restrict__ A_log,
                            const float* __restrict__ dt_bias) {
    int gw   = (blockIdx.x * blockDim.x + threadIdx.x) >> 5;
    int lane = threadIdx.x & 31;
    if (gw >= TT * HH) return;
    int t = gw >> 4;
    int h = gw & 15;
    int d = lane * 4;
    int cq = h * DKK + d;

    float qy[4], ky[4], vy[4];
    conv_silu4(qkv, w, t, cq,        qy);
    conv_silu4(qkv, w, t, cq + 2048, ky);
    conv_silu4(qkv, w, t, cq + 4096, vy);

    // l2norm sums
    float sq = 0.f, sk = 0.f;
#pragma unroll
    for (int j = 0; j < 4; j++) {
        sq = fmaf(qy[j], qy[j], sq);
        sk = fmaf(ky[j], ky[j], sk);
    }
#pragma unroll
    for (int m = 16; m > 0; m >>= 1) {
        sq += __shfl_xor_sync(0xffffffffu, sq, m);
        sk += __shfl_xor_sync(0xffffffffu, sk, m);
    }
    float se_q = sq + 1e-6f, se_k = sk + 1e-6f;
    float rq = rsqrtf(se_q); rq = rq * (1.5f - 0.5f * se_q * rq * rq);  // Newton
    float rk = rsqrtf(se_k); rk = rk * (1.5f - 0.5f * se_k * rk * rk);
    rq *= 0.08838834764831845f;   // DK^-0.5

    // gate
    float ea = expf(A_log[h]);
    float4 fgv = *(const float4*)(fg + (size_t)t * (HH * DKK) + h * DKK + d);
    float4 dbv = *(const float4*)(dt_bias + h * DKK + d);
    float zf[4] = {fgv.x + dbv.x, fgv.y + dbv.y, fgv.z + dbv.z, fgv.w + dbv.w};

    float bb = 1.f / (1.f + expf(-beta[t * HH + h]));

    float qn[4], kn[4], av[4], kav[4];
#pragma unroll
    for (int j = 0; j < 4; j++) {
        float z  = zf[j];
        float sp = (z > 20.f) ? z : log1pf(expf(z));   // softplus
        av[j]  = expf(-ea * sp);                       // a = exp(g)
        qn[j]  = qy[j] * rq;
        kn[j]  = ky[j] * rk;
        kav[j] = kn[j] * av[j];
    }

    size_t pb = ((size_t)t * HH + h) * 512 + d;
    *(float4*)(g_P + pb      ) = make_float4(kav[0], kav[1], kav[2], kav[3]);
    *(float4*)(g_P + pb + 128) = make_float4(av[0],  av[1],  av[2],  av[3]);
    *(float4*)(g_P + pb + 256) = make_float4(kn[0],  kn[1],  kn[2],  kn[3]);
    *(float4*)(g_P + pb + 384) = make_float4(qn[0],  qn[1],  qn[2],  qn[3]);
    *(float4*)(g_BV + ((size_t)t * HH + h) * DKK + d) =
        make_float4(vy[0] * bb, vy[1] * bb, vy[2] * bb, vy[3] * bb);
    if (lane == 0)
        g_B[t * HH + h] = bb;
}

// --------------------------------------------------------------------------
// Kernel 1b: lookahead precompute. One warp per (t,h).
//   w_t = ka_t ∘ a_{t-1} ∘ a_{t-2}      (overwrite slot0 in place)
//   R_t = (ka_t ∘ a_{t-1}) · k_{t-2}    (scalar)
//   Q_t = ka_t · k_{t-1}                (scalar)
// Negative t indices: a := 1, k := 0.
// --------------------------------------------------------------------------
__global__ void pass2_kernel() {
    int gw   = (blockIdx.x * blockDim.x + threadIdx.x) >> 5;
    int lane = threadIdx.x & 31;
    if (gw >= TT * HH) return;
    int t = gw >> 4;
    int h = gw & 15;
    int d = lane * 4;

    size_t bt = ((size_t)t * HH + h) * 512;
    const size_t ts = (size_t)HH * 512;

    float4 ka = *(const float4*)(g_P + bt + d);
    float4 a1 = make_float4(1.f, 1.f, 1.f, 1.f);
    float4 a2 = make_float4(1.f, 1.f, 1.f, 1.f);
    float4 k1 = make_float4(0.f, 0.f, 0.f, 0.f);
    float4 k2 = make_float4(0.f, 0.f, 0.f, 0.f);
    if (t >= 1) {
        a1 = *(const float4*)(g_P + bt - ts + 128 + d);
        k1 = *(const float4*)(g_P + bt - ts + 256 + d);
    }
    if (t >= 2) {
        a2 = *(const float4*)(g_P + bt - 2 * ts + 128 + d);
        k2 = *(const float4*)(g_P + bt - 2 * ts + 256 + d);
    }
    float4 u = make_float4(ka.x * a1.x, ka.y * a1.y, ka.z * a1.z, ka.w * a1.w);
    float4 wv = make_float4(u.x * a2.x, u.y * a2.y, u.z * a2.z, u.w * a2.w);

    float rp = fmaf(u.x, k2.x, u.y * k2.y) + fmaf(u.z, k2.z, u.w * k2.w);
    float qp = fmaf(ka.x, k1.x, ka.y * k1.y) + fmaf(ka.z, k1.z, ka.w * k1.w);
#pragma unroll
    for (int m = 16; m > 0; m >>= 1) {
        rp += __shfl_xor_sync(0xffffffffu, rp, m);
        qp += __shfl_xor_sync(0xffffffffu, qp, m);
    }
    *(float4*)(g_P + bt + d) = wv;            // slot0 := w (safe: private)
    if (lane == 0)
        *(float4*)(g_S4 + ((size_t)t * HH + h) * 4) =
            make_float4(g_B[t * HH + h], rp, qp, 0.f);
}

// --------------------------------------------------------------------------
// Kernel 2: gated delta-rule recurrence with 3-step lookahead.
// One warp = 4 v-columns; lane = cg*8 + kg. Lane's k-slice: 16 values
// (8 f32x2 pairs): k = j*32 + kg*4 + (0..3), j = 0..3.
//
// Critical chain per step (3 FFMAs only):
//   r_t  = P_t + d2*R_t + d1*Q_t;  dt = bv_t - b_t*r_t
// P_t = w_t · S_{t-3} is computed+reduced 3 iterations early (off-chain),
// fused into the same register pass as the S update and o-dot.
// --------------------------------------------------------------------------
#define STGF 544   // floats per stage: 512 packed + 16 bv + 4 scalars + pad
#define NST  16    // 4 groups x 4 steps in-flight ring

__global__ void __launch_bounds__(128, 1)
recur_kernel(float* __restrict__ out) {
    __shared__ __align__(16) float sm[NST * STGF];

    const int tid  = threadIdx.x;
    const int warp = tid >> 5;
    const int lane = tid & 31;
    const int kg   = lane & 7;
    const int cg   = lane >> 3;
    const int h    = blockIdx.x >> 3;
    const int vb   = (blockIdx.x & 7) * 16;       // CTA's 16-column slab
    const int vcol = vb + warp * 4 + cg;
    float* outp = out + h * DKK + vcol;

    auto issue = [&](int g) {
#pragma unroll
        for (int s = 0; s < 4; s++) {
            int tu = 4 * g + s;
            float* sp = sm + (tu & 15) * STGF;
            int t = (tu > TT - 1) ? (TT - 1) : tu;
            const float* gp = g_P + ((size_t)t * HH + h) * 512;
            cp16(sp + tid * 4, gp + tid * 4);
            if (tid < 4)
                cp16(sp + 512 + tid * 4,
                     g_BV + ((size_t)t * HH + h) * DKK + vb + tid * 4);
            if (tid == 4)
                cp16(sp + 528, g_S4 + ((size_t)t * HH + h) * 4);
        }
        asm volatile("cp.async.commit_group;" ::: "memory");
    };

    issue(0); issue(1); issue(2);

    unsigned long long S[8] = {0, 0, 0, 0, 0, 0, 0, 0};
    float Pq[4] = {0.f, 0.f, 0.f, 0.f};   // reduced P for steps t..t+3
    float d1 = 0.f, d2 = 0.f;             // delta_{t-1}, delta_{t-2}

    for (int g = 0; g < TT / 4; g++) {
        // groups g and g+1 complete (w of t+3 lives in group g+1)
        asm volatile("cp.async.wait_group 1;" ::: "memory");
        __syncthreads();
#pragma unroll
        for (int s = 0; s < 4; s++) {
            const int t = 4 * g + s;
            const float* spb = sm + (t & 15) * STGF;
            const float* sp  = spb + kg * 4;
            const float* wnb = sm + ((t + 3) & 15) * STGF + kg * 4; // w_{t+3}

            float4 s4 = *(const float4*)(spb + 528);    // {b, R, Q, -}
            float  bv = spb[512 + warp * 4 + cg];

            // ---- critical chain: 3 dependent FFMAs ----
            float r  = fmaf(d2, s4.y, Pq[s]);
            r        = fmaf(d1, s4.z, r);
            float dt = fmaf(-s4.x, r, bv);
            d2 = d1; d1 = dt;
            unsigned long long D2 = pack2(dt);

            // ---- off-chain: S update fused with o-dot and P_{t+3}-dot ----
            ulonglong2 A[4], K[4], Q[4], W[4];
#pragma unroll
            for (int j = 0; j < 4; j++) {
                A[j] = *(const ulonglong2*)(sp + 128 + j * 32);
                K[j] = *(const ulonglong2*)(sp + 256 + j * 32);
                Q[j] = *(const ulonglong2*)(sp + 384 + j * 32);
                W[j] = *(const ulonglong2*)(wnb + j * 32);
            }
            unsigned long long o0 = 0ull, o1 = 0ull, p0 = 0ull, p1 = 0ull;
#pragma unroll
            for (int j = 0; j < 4; j++) {
                S[2*j]   = ffma2(A[j].x, S[2*j],   fmul2(K[j].x, D2));
                S[2*j+1] = ffma2(A[j].y, S[2*j+1], fmul2(K[j].y, D2));
                o0 = ffma2(Q[j].x, S[2*j],   o0);
                o1 = ffma2(Q[j].y, S[2*j+1], o1);
                p0 = ffma2(W[j].x, S[2*j],   p0);
                p1 = ffma2(W[j].y, S[2*j+1], p1);
            }
            float ov = hsum2(fadd2(o0, o1));
            float pv = hsum2(fadd2(p0, p1));
            // 3-level butterfly over kg; two interleaved chains (off-chain)
#pragma unroll
            for (int m = 1; m < 8; m <<= 1) {
                ov += __shfl_xor_sync(0xffffffffu, ov, m);
                pv += __shfl_xor_sync(0xffffffffu, pv, m);
            }
            Pq[(s + 3) & 3] = pv;          // P_{t+3} = w_{t+3} . S_t
            if (kg == 0) outp[(size_t)t * (HH * DKK)] = ov;
        }
        issue(g + 3);
    }
}

// --------------------------------------------------------------------------
extern "C" void kernel_launch(void* const* d_in, const int* in_sizes, int n_in,
                              void* d_out, int out_size) {
    const float* mixed_qkv   = (const float*)d_in[0];
    const float* forget_gate = (const float*)d_in[1];
    const float* beta        = (const float*)d_in[2];
    const float* conv_w      = (const float*)d_in[3];
    const float* A_log       = (const float*)d_in[4];
    const float* dt_bias     = (const float*)d_in[5];
    float* out = (float*)d_out;

    prep_kernel<<<(TT * HH) / 8, 256>>>(mixed_qkv, forget_gate, beta,
                                        conv_w, A_log, dt_bias);
    pass2_kernel<<<(TT * HH) / 8, 256>>>();
    recur_kernel<<<128, 128>>>(out);
}

// round 7
// speedup vs baseline: 2.6744x; 1.1748x over previous
#include <cuda_runtime.h>
#include <cuda_bf16.h>

// Problem constants
#define TT   4096
#define HH   16
#define DKK  128
#define QKVC 6144
#define NELEM (TT * HH * DKK)   // 8388608

// Scratch (static __device__ globals — no runtime allocation)
// g_P packed per (t,h): [slot0(128) | a(128) | k(128) | q(128)]
// slot0 holds ka after prep; pass2 overwrites it in place with
// w_t = ka_t ∘ a_{t-1} ∘ a_{t-2} (only warp (t,h) ever touches slot0 of (t,h)).
__device__ __align__(16) float g_P [TT * HH * 512];
__device__ __align__(16) float g_BV[NELEM];        // b * (conv+silu v)
__device__ __align__(16) float g_S4[TT * HH * 4];  // {b, R, Q, 0} per (t,h)
__device__ float g_B[TT * HH];                     // sigmoid(beta)

// --------------------------------------------------------------------------
// f32x2 packed-math helpers (FFMA2 path; ptxas only emits via PTX f32x2)
// --------------------------------------------------------------------------
__device__ __forceinline__ unsigned long long ffma2(unsigned long long a,
                                                    unsigned long long b,
                                                    unsigned long long c) {
    unsigned long long d;
    asm("fma.rn.f32x2 %0, %1, %2, %3;" : "=l"(d) : "l"(a), "l"(b), "l"(c));
    return d;
}
__device__ __forceinline__ unsigned long long fmul2(unsigned long long a,
                                                    unsigned long long b) {
    unsigned long long d;
    asm("mul.rn.f32x2 %0, %1, %2;" : "=l"(d) : "l"(a), "l"(b));
    return d;
}
__device__ __forceinline__ unsigned long long fadd2(unsigned long long a,
                                                    unsigned long long b) {
    unsigned long long d;
    asm("add.rn.f32x2 %0, %1, %2;" : "=l"(d) : "l"(a), "l"(b));
    return d;
}
__device__ __forceinline__ float hsum2(unsigned long long a) {
    float lo, hi;
    asm("mov.b64 {%0, %1}, %2;" : "=f"(lo), "=f"(hi) : "l"(a));
    return lo + hi;
}
__device__ __forceinline__ unsigned long long pack2(float x) {
    unsigned long long d;
    asm("mov.b64 %0, {%1, %1};" : "=l"(d) : "f"(x));
    return d;
}

// cp.async helper
__device__ __forceinline__ void cp16(float* dst, const float* src) {
    unsigned d = (unsigned)__cvta_generic_to_shared(dst);
    asm volatile("cp.async.cg.shared.global [%0], [%1], 16;"
                 :: "r"(d), "l"(src) : "memory");
}

// --------------------------------------------------------------------------
// Kernel 1: conv1d(K=4, depthwise, causal) + SiLU + l2norm + gate precompute
// One warp per (t, h); lane handles 4 consecutive d via float4.
// --------------------------------------------------------------------------
__device__ __forceinline__ void conv_silu4(const float* __restrict__ x,
                                           const float* __restrict__ w,
                                           int t, int c, float out[4]) {
    float wz[4][4];
#pragma unroll
    for (int j = 0; j < 4; j++) {
        float4 wv = *(const float4*)(w + (size_t)(c + j) * 4);
        wz[j][0] = wv.x; wz[j][1] = wv.y; wz[j][2] = wv.z; wz[j][3] = wv.w;
    }
    float acc[4] = {0.f, 0.f, 0.f, 0.f};
#pragma unroll
    for (int tau = 0; tau < 4; tau++) {
        int tt = t - 3 + tau;
        if (tt >= 0) {
            float4 xv = *(const float4*)(x + (size_t)tt * QKVC + c);
            acc[0] = fmaf(xv.x, wz[0][tau], acc[0]);
            acc[1] = fmaf(xv.y, wz[1][tau], acc[1]);
            acc[2] = fmaf(xv.z, wz[2][tau], acc[2]);
            acc[3] = fmaf(xv.w, wz[3][tau], acc[3]);
        }
    }
#pragma unroll
    for (int j = 0; j < 4; j++)
        out[j] = acc[j] / (1.f + expf(-acc[j]));   // SiLU
}

__global__ void prep_kernel(const float* __restrict__ qkv,
                            const float* __restrict__ fg,
                            const float* __restrict__ beta,
                            const float* __restrict__ w,
                            const float* __restrict__ A_log,
                            const float* __restrict__ dt_bias) {
    int gw   = (blockIdx.x * blockDim.x + threadIdx.x) >> 5;
    int lane = threadIdx.x & 31;
    if (gw >= TT * HH) return;
    int t = gw >> 4;
    int h = gw & 15;
    int d = lane * 4;
    int cq = h * DKK + d;

    float qy[4], ky[4], vy[4];
    conv_silu4(qkv, w, t, cq,        qy);
    conv_silu4(qkv, w, t, cq + 2048, ky);
    conv_silu4(qkv, w, t, cq + 4096, vy);

    // l2norm sums
    float sq = 0.f, sk = 0.f;
#pragma unroll
    for (int j = 0; j < 4; j++) {
        sq = fmaf(qy[j], qy[j], sq);
        sk = fmaf(ky[j], ky[j], sk);
    }
#pragma unroll
    for (int m = 16; m > 0; m >>= 1) {
        sq += __shfl_xor_sync(0xffffffffu, sq, m);
        sk += __shfl_xor_sync(0xffffffffu, sk, m);
    }
    float se_q = sq + 1e-6f, se_k = sk + 1e-6f;
    float rq = rsqrtf(se_q); rq = rq * (1.5f - 0.5f * se_q * rq * rq);  // Newton
    float rk = rsqrtf(se_k); rk = rk * (1.5f - 0.5f * se_k * rk * rk);
    rq *= 0.08838834764831845f;   // DK^-0.5

    // gate
    float ea = expf(A_log[h]);
    float4 fgv = *(const float4*)(fg + (size_t)t * (HH * DKK) + h * DKK + d);
    float4 dbv = *(const float4*)(dt_bias + h * DKK + d);
    float zf[4] = {fgv.x + dbv.x, fgv.y + dbv.y, fgv.z + dbv.z, fgv.w + dbv.w};

    float bb = 1.f / (1.f + expf(-beta[t * HH + h]));

    float qn[4], kn[4], av[4], kav[4];
#pragma unroll
    for (int j = 0; j < 4; j++) {
        float z  = zf[j];
        float sp = (z > 20.f) ? z : log1pf(expf(z));   // softplus
        av[j]  = expf(-ea * sp);                       // a = exp(g)
        qn[j]  = qy[j] * rq;
        kn[j]  = ky[j] * rk;
        kav[j] = kn[j] * av[j];
    }

    size_t pb = ((size_t)t * HH + h) * 512 + d;
    *(float4*)(g_P + pb      ) = make_float4(kav[0], kav[1], kav[2], kav[3]);
    *(float4*)(g_P + pb + 128) = make_float4(av[0],  av[1],  av[2],  av[3]);
    *(float4*)(g_P + pb + 256) = make_float4(kn[0],  kn[1],  kn[2],  kn[3]);
    *(float4*)(g_P + pb + 384) = make_float4(qn[0],  qn[1],  qn[2],  qn[3]);
    *(float4*)(g_BV + ((size_t)t * HH + h) * DKK + d) =
        make_float4(vy[0] * bb, vy[1] * bb, vy[2] * bb, vy[3] * bb);
    if (lane == 0)
        g_B[t * HH + h] = bb;
}

// --------------------------------------------------------------------------
// Kernel 1b: lookahead precompute. One warp per (t,h).
//   w_t = ka_t ∘ a_{t-1} ∘ a_{t-2}      (overwrite slot0 in place)
//   R_t = (ka_t ∘ a_{t-1}) · k_{t-2}    (scalar)
//   Q_t = ka_t · k_{t-1}                (scalar)
// Negative t indices: a := 1, k := 0.
// --------------------------------------------------------------------------
__global__ void pass2_kernel() {
    int gw   = (blockIdx.x * blockDim.x + threadIdx.x) >> 5;
    int lane = threadIdx.x & 31;
    if (gw >= TT * HH) return;
    int t = gw >> 4;
    int h = gw & 15;
    int d = lane * 4;

    size_t bt = ((size_t)t * HH + h) * 512;
    const size_t ts = (size_t)HH * 512;

    float4 ka = *(const float4*)(g_P + bt + d);
    float4 a1 = make_float4(1.f, 1.f, 1.f, 1.f);
    float4 a2 = make_float4(1.f, 1.f, 1.f, 1.f);
    float4 k1 = make_float4(0.f, 0.f, 0.f, 0.f);
    float4 k2 = make_float4(0.f, 0.f, 0.f, 0.f);
    if (t >= 1) {
        a1 = *(const float4*)(g_P + bt - ts + 128 + d);
        k1 = *(const float4*)(g_P + bt - ts + 256 + d);
    }
    if (t >= 2) {
        a2 = *(const float4*)(g_P + bt - 2 * ts + 128 + d);
        k2 = *(const float4*)(g_P + bt - 2 * ts + 256 + d);
    }
    float4 u = make_float4(ka.x * a1.x, ka.y * a1.y, ka.z * a1.z, ka.w * a1.w);
    float4 wv = make_float4(u.x * a2.x, u.y * a2.y, u.z * a2.z, u.w * a2.w);

    float rp = fmaf(u.x, k2.x, u.y * k2.y) + fmaf(u.z, k2.z, u.w * k2.w);
    float qp = fmaf(ka.x, k1.x, ka.y * k1.y) + fmaf(ka.z, k1.z, ka.w * k1.w);
#pragma unroll
    for (int m = 16; m > 0; m >>= 1) {
        rp += __shfl_xor_sync(0xffffffffu, rp, m);
        qp += __shfl_xor_sync(0xffffffffu, qp, m);
    }
    *(float4*)(g_P + bt + d) = wv;            // slot0 := w (safe: private)
    if (lane == 0)
        *(float4*)(g_S4 + ((size_t)t * HH + h) * 4) =
            make_float4(g_B[t * HH + h], rp, qp, 0.f);
}

// --------------------------------------------------------------------------
// Kernel 2: gated delta-rule recurrence with 3-step lookahead.
// CTA = 256 threads (8 warps) = 16 v-columns; one warp = 2 v-columns.
// lane = cg*16 + kg; cg in [0,2) = column, kg in [0,16) = k group.
// Lane's k-slice: 8 floats (4 f32x2 pairs): k = j*64 + kg*4 + (0..3), j=0,1.
// Reduction over kg = 4 butterfly levels (masks 1,2,4,8 — stay within half).
//
// Critical chain per step (3 dependent FFMAs):
//   r_t = P_t + d2*R_t + d1*Q_t;  dt = bv_t - b_t*r_t
// P_t = w_t · S_{t-3} is computed+reduced 3 iterations early (off-chain),
// fused into the same register pass as the S update and o-dot.
// --------------------------------------------------------------------------
#define STGF 544   // floats per stage: 512 packed + 16 bv + 4 scalars + pad
#define NST  16    // 4 groups x 4 steps in-flight ring

__global__ void __launch_bounds__(256, 1)
recur_kernel(float* __restrict__ out) {
    __shared__ __align__(16) float sm[NST * STGF];

    const int tid  = threadIdx.x;
    const int warp = tid >> 5;
    const int lane = tid & 31;
    const int kg   = lane & 15;
    const int cg   = lane >> 4;
    const int h    = blockIdx.x >> 3;
    const int vb   = (blockIdx.x & 7) * 16;       // CTA's 16-column slab
    const int vcol = vb + warp * 2 + cg;
    float* outp = out + h * DKK + vcol;

    auto issue = [&](int g) {
#pragma unroll
        for (int s = 0; s < 4; s++) {
            int tu = 4 * g + s;
            float* sp = sm + (tu & 15) * STGF;
            int t = (tu > TT - 1) ? (TT - 1) : tu;
            const float* gp = g_P + ((size_t)t * HH + h) * 512;
            if (tid < 128) cp16(sp + tid * 4, gp + tid * 4);
            if (tid >= 128 && tid < 132)
                cp16(sp + 512 + (tid - 128) * 4,
                     g_BV + ((size_t)t * HH + h) * DKK + vb + (tid - 128) * 4);
            if (tid == 132)
                cp16(sp + 528, g_S4 + ((size_t)t * HH + h) * 4);
        }
        asm volatile("cp.async.commit_group;" ::: "memory");
    };

    issue(0); issue(1); issue(2);

    unsigned long long S[4] = {0, 0, 0, 0};
    float Pq[4] = {0.f, 0.f, 0.f, 0.f};   // reduced P for steps t..t+3
    float d1 = 0.f, d2 = 0.f;             // delta_{t-1}, delta_{t-2}

    for (int g = 0; g < TT / 4; g++) {
        // groups g and g+1 complete (w of t+3 lives in group g+1)
        asm volatile("cp.async.wait_group 1;" ::: "memory");
        __syncthreads();
#pragma unroll
        for (int s = 0; s < 4; s++) {
            const int t = 4 * g + s;
            const float* spb = sm + (t & 15) * STGF;
            const float* sp  = spb + kg * 4;
            const float* wnb = sm + ((t + 3) & 15) * STGF + kg * 4; // w_{t+3}

            float4 s4 = *(const float4*)(spb + 528);    // {b, R, Q, -}
            float  bv = spb[512 + warp * 2 + cg];

            // ---- critical chain: 3 dependent FFMAs ----
            float r  = fmaf(d2, s4.y, Pq[s]);
            r        = fmaf(d1, s4.z, r);
            float dt = fmaf(-s4.x, r, bv);
            d2 = d1; d1 = dt;
            unsigned long long D2 = pack2(dt);

            // ---- off-chain: S update fused with o-dot and P_{t+3}-dot ----
            ulonglong2 A[2], K[2], Q[2], W[2];
#pragma unroll
            for (int j = 0; j < 2; j++) {
                A[j] = *(const ulonglong2*)(sp + 128 + j * 64);
                K[j] = *(const ulonglong2*)(sp + 256 + j * 64);
                Q[j] = *(const ulonglong2*)(sp + 384 + j * 64);
                W[j] = *(const ulonglong2*)(wnb + j * 64);
            }
            unsigned long long o0 = 0ull, o1 = 0ull, p0 = 0ull, p1 = 0ull;
#pragma unroll
            for (int j = 0; j < 2; j++) {
                S[2*j]   = ffma2(A[j].x, S[2*j],   fmul2(K[j].x, D2));
                S[2*j+1] = ffma2(A[j].y, S[2*j+1], fmul2(K[j].y, D2));
                o0 = ffma2(Q[j].x, S[2*j],   o0);
                o1 = ffma2(Q[j].y, S[2*j+1], o1);
                p0 = ffma2(W[j].x, S[2*j],   p0);
                p1 = ffma2(W[j].y, S[2*j+1], p1);
            }
            float ov = hsum2(fadd2(o0, o1));
            float pv = hsum2(fadd2(p0, p1));
            // 4-level butterfly over kg; two interleaved chains (off-chain)
#pragma unroll
            for (int m = 1; m < 16; m <<= 1) {
                ov += __shfl_xor_sync(0xffffffffu, ov, m);
                pv += __shfl_xor_sync(0xffffffffu, pv, m);
            }
            Pq[(s + 3) & 3] = pv;          // P_{t+3} = w_{t+3} . S_t
            if (kg == 0) outp[(size_t)t * (HH * DKK)] = ov;
        }
        issue(g + 3);
    }
}

// --------------------------------------------------------------------------
extern "C" void kernel_launch(void* const* d_in, const int* in_sizes, int n_in,
                              void* d_out, int out_size) {
    const float* mixed_qkv   = (const float*)d_in[0];
    const float* forget_gate = (const float*)d_in[1];
    const float* beta        = (const float*)d_in[2];
    const float* conv_w      = (const float*)d_in[3];
    const float* A_log       = (const float*)d_in[4];
    const float* dt_bias     = (const float*)d_in[5];
    float* out = (float*)d_out;

    prep_kernel<<<(TT * HH) / 8, 256>>>(mixed_qkv, forget_gate, beta,
                                        conv_w, A_log, dt_bias);
    pass2_kernel<<<(TT * HH) / 8, 256>>>();
    recur_kernel<<<128, 256>>>(out);
}

// round 8
// speedup vs baseline: 2.8107x; 1.0509x over previous
#include <cuda_runtime.h>
#include <cuda_bf16.h>

// Problem constants
#define TT   4096
#define HH   16
#define DKK  128
#define QKVC 6144
#define NELEM (TT * HH * DKK)   // 8388608

// Scratch (static __device__ globals — no runtime allocation)
// g_P packed per (t,h): [slot0(128) | a(128) | k(128) | q(128)]
// slot0 holds ka after prep; pass2 overwrites it in place with
// w_t = ka_t ∘ a_{t-1} ∘ a_{t-2} (only warp (t,h) ever touches slot0 of (t,h)).
__device__ __align__(16) float g_P [TT * HH * 512];
__device__ __align__(16) float g_BV[NELEM];        // b * (conv+silu v)
__device__ __align__(16) float g_S4[TT * HH * 4];  // {b, R, Q, 0} per (t,h)
__device__ float g_B[TT * HH];                     // sigmoid(beta)

typedef unsigned long long ull;

// --------------------------------------------------------------------------
// f32x2 packed-math helpers (FFMA2 path; ptxas only emits via PTX f32x2)
// --------------------------------------------------------------------------
__device__ __forceinline__ ull ffma2(ull a, ull b, ull c) {
    ull d;
    asm("fma.rn.f32x2 %0, %1, %2, %3;" : "=l"(d) : "l"(a), "l"(b), "l"(c));
    return d;
}
__device__ __forceinline__ ull fmul2(ull a, ull b) {
    ull d;
    asm("mul.rn.f32x2 %0, %1, %2;" : "=l"(d) : "l"(a), "l"(b));
    return d;
}
__device__ __forceinline__ ull fadd2(ull a, ull b) {
    ull d;
    asm("add.rn.f32x2 %0, %1, %2;" : "=l"(d) : "l"(a), "l"(b));
    return d;
}
__device__ __forceinline__ float hsum2(ull a) {
    float lo, hi;
    asm("mov.b64 {%0, %1}, %2;" : "=f"(lo), "=f"(hi) : "l"(a));
    return lo + hi;
}
__device__ __forceinline__ ull pack2(float x) {
    ull d;
    asm("mov.b64 %0, {%1, %1};" : "=l"(d) : "f"(x));
    return d;
}
__device__ __forceinline__ ull packAB(float a, float b) {
    ull d;
    asm("mov.b64 %0, {%1, %2};" : "=l"(d) : "f"(a), "f"(b));
    return d;
}
__device__ __forceinline__ void unpack2(float& lo, float& hi, ull a) {
    asm("mov.b64 {%0, %1}, %2;" : "=f"(lo), "=f"(hi) : "l"(a));
}
__device__ __forceinline__ ull shfl64(ull v, int m) {
    float lo, hi;
    unpack2(lo, hi, v);
    lo = __shfl_xor_sync(0xffffffffu, lo, m);
    hi = __shfl_xor_sync(0xffffffffu, hi, m);
    return packAB(lo, hi);
}

// cp.async helper
__device__ __forceinline__ void cp16(float* dst, const float* src) {
    unsigned d = (unsigned)__cvta_generic_to_shared(dst);
    asm volatile("cp.async.cg.shared.global [%0], [%1], 16;"
                 :: "r"(d), "l"(src) : "memory");
}

// --------------------------------------------------------------------------
// Kernel 1: conv1d(K=4, depthwise, causal) + SiLU + l2norm + gate precompute
// One warp per (t, h); lane handles 4 consecutive d via float4.
// --------------------------------------------------------------------------
__device__ __forceinline__ void conv_silu4(const float* __restrict__ x,
                                           const float* __restrict__ w,
                                           int t, int c, float out[4]) {
    float wz[4][4];
#pragma unroll
    for (int j = 0; j < 4; j++) {
        float4 wv = *(const float4*)(w + (size_t)(c + j) * 4);
        wz[j][0] = wv.x; wz[j][1] = wv.y; wz[j][2] = wv.z; wz[j][3] = wv.w;
    }
    float acc[4] = {0.f, 0.f, 0.f, 0.f};
#pragma unroll
    for (int tau = 0; tau < 4; tau++) {
        int tt = t - 3 + tau;
        if (tt >= 0) {
            float4 xv = *(const float4*)(x + (size_t)tt * QKVC + c);
            acc[0] = fmaf(xv.x, wz[0][tau], acc[0]);
            acc[1] = fmaf(xv.y, wz[1][tau], acc[1]);
            acc[2] = fmaf(xv.z, wz[2][tau], acc[2]);
            acc[3] = fmaf(xv.w, wz[3][tau], acc[3]);
        }
    }
#pragma unroll
    for (int j = 0; j < 4; j++)
        out[j] = acc[j] / (1.f + expf(-acc[j]));   // SiLU
}

__global__ void prep_kernel(const float* __restrict__ qkv,
                            const float* __restrict__ fg,
                            const float* __restrict__ beta,
                            const float* __restrict__ w,
                            const float* __restrict__ A_log,
                            const float* __restrict__ dt_bias) {
    int gw   = (blockIdx.x * blockDim.x + threadIdx.x) >> 5;
    int lane = threadIdx.x & 31;
    if (gw >= TT * HH) return;
    int t = gw >> 4;
    int h = gw & 15;
    int d = lane * 4;
    int cq = h * DKK + d;

    float qy[4], ky[4], vy[4];
    conv_silu4(qkv, w, t, cq,        qy);
    conv_silu4(qkv, w, t, cq + 2048, ky);
    conv_silu4(qkv, w, t, cq + 4096, vy);

    // l2norm sums
    float sq = 0.f, sk = 0.f;
#pragma unroll
    for (int j = 0; j < 4; j++) {
        sq = fmaf(qy[j], qy[j], sq);
        sk = fmaf(ky[j], ky[j], sk);
    }
#pragma unroll
    for (int m = 16; m > 0; m >>= 1) {
        sq += __shfl_xor_sync(0xffffffffu, sq, m);
        sk += __shfl_xor_sync(0xffffffffu, sk, m);
    }
    float se_q = sq + 1e-6f, se_k = sk + 1e-6f;
    float rq = rsqrtf(se_q); rq = rq * (1.5f - 0.5f * se_q * rq * rq);  // Newton
    float rk = rsqrtf(se_k); rk = rk * (1.5f - 0.5f * se_k * rk * rk);
    rq *= 0.08838834764831845f;   // DK^-0.5

    // gate
    float ea = expf(A_log[h]);
    float4 fgv = *(const float4*)(fg + (size_t)t * (HH * DKK) + h * DKK + d);
    float4 dbv = *(const float4*)(dt_bias + h * DKK + d);
    float zf[4] = {fgv.x + dbv.x, fgv.y + dbv.y, fgv.z + dbv.z, fgv.w + dbv.w};

    float bb = 1.f / (1.f + expf(-beta[t * HH + h]));

    float qn[4], kn[4], av[4], kav[4];
#pragma unroll
    for (int j = 0; j < 4; j++) {
        float z  = zf[j];
        float sp = (z > 20.f) ? z : log1pf(expf(z));   // softplus
        av[j]  = expf(-ea * sp);                       // a = exp(g)
        qn[j]  = qy[j] * rq;
        kn[j]  = ky[j] * rk;
        kav[j] = kn[j] * av[j];
    }

    size_t pb = ((size_t)t * HH + h) * 512 + d;
    *(float4*)(g_P + pb      ) = make_float4(kav[0], kav[1], kav[2], kav[3]);
    *(float4*)(g_P + pb + 128) = make_float4(av[0],  av[1],  av[2],  av[3]);
    *(float4*)(g_P + pb + 256) = make_float4(kn[0],  kn[1],  kn[2],  kn[3]);
    *(float4*)(g_P + pb + 384) = make_float4(qn[0],  qn[1],  qn[2],  qn[3]);
    *(float4*)(g_BV + ((size_t)t * HH + h) * DKK + d) =
        make_float4(vy[0] * bb, vy[1] * bb, vy[2] * bb, vy[3] * bb);
    if (lane == 0)
        g_B[t * HH + h] = bb;
}

// --------------------------------------------------------------------------
// Kernel 1b: lookahead precompute. One warp per (t,h).
//   w_t = ka_t ∘ a_{t-1} ∘ a_{t-2}      (overwrite slot0 in place)
//   R_t = (ka_t ∘ a_{t-1}) · k_{t-2}    (scalar)
//   Q_t = ka_t · k_{t-1}                (scalar)
// Negative t indices: a := 1, k := 0.
// --------------------------------------------------------------------------
__global__ void pass2_kernel() {
    int gw   = (blockIdx.x * blockDim.x + threadIdx.x) >> 5;
    int lane = threadIdx.x & 31;
    if (gw >= TT * HH) return;
    int t = gw >> 4;
    int h = gw & 15;
    int d = lane * 4;

    size_t bt = ((size_t)t * HH + h) * 512;
    const size_t ts = (size_t)HH * 512;

    float4 ka = *(const float4*)(g_P + bt + d);
    float4 a1 = make_float4(1.f, 1.f, 1.f, 1.f);
    float4 a2 = make_float4(1.f, 1.f, 1.f, 1.f);
    float4 k1 = make_float4(0.f, 0.f, 0.f, 0.f);
    float4 k2 = make_float4(0.f, 0.f, 0.f, 0.f);
    if (t >= 1) {
        a1 = *(const float4*)(g_P + bt - ts + 128 + d);
        k1 = *(const float4*)(g_P + bt - ts + 256 + d);
    }
    if (t >= 2) {
        a2 = *(const float4*)(g_P + bt - 2 * ts + 128 + d);
        k2 = *(const float4*)(g_P + bt - 2 * ts + 256 + d);
    }
    float4 u = make_float4(ka.x * a1.x, ka.y * a1.y, ka.z * a1.z, ka.w * a1.w);
    float4 wv = make_float4(u.x * a2.x, u.y * a2.y, u.z * a2.z, u.w * a2.w);

    float rp = fmaf(u.x, k2.x, u.y * k2.y) + fmaf(u.z, k2.z, u.w * k2.w);
    float qp = fmaf(ka.x, k1.x, ka.y * k1.y) + fmaf(ka.z, k1.z, ka.w * k1.w);
#pragma unroll
    for (int m = 16; m > 0; m >>= 1) {
        rp += __shfl_xor_sync(0xffffffffu, rp, m);
        qp += __shfl_xor_sync(0xffffffffu, qp, m);
    }
    *(float4*)(g_P + bt + d) = wv;            // slot0 := w (safe: private)
    if (lane == 0)
        *(float4*)(g_S4 + ((size_t)t * HH + h) * 4) =
            make_float4(g_B[t * HH + h], rp, qp, 0.f);
}

// --------------------------------------------------------------------------
// Kernel 2: gated delta-rule recurrence with 3-step lookahead.
// CTA = 256 threads (8 warps) = 16 v-columns; one warp = 2 v-columns.
// Lane owns k-quad 4*lane..4*lane+3 — array loads are DISTINCT per lane
// (one LDS.128 per array covers the whole 128-vector, no broadcast
// duplication -> half the smem crossbar bytes of the previous layout).
// State: SA/SB = S[4 ki][colA/colB] as ki-paired f32x2 (float4 reinterprets
// directly to ulonglong2, no pack overhead).
// Dot reductions: 5-level 64-bit butterfly on (colA,colB)-packed partials,
// o-dot and P-dot interleaved, both off the critical chain.
// Critical chain per step: 3 dependent packed FFMA2s:
//   r_t = P_t + d2*R_t + d1*Q_t;  dt = bv_t - b_t*r_t
// --------------------------------------------------------------------------
#define STGF 544   // floats per stage: 512 packed + 16 bv + 4 scalars + pad
#define NST  16    // 4 groups x 4 steps in-flight ring

__global__ void __launch_bounds__(256, 1)
recur_kernel(float* __restrict__ out) {
    __shared__ __align__(16) float sm[NST * STGF];

    const int tid  = threadIdx.x;
    const int warp = tid >> 5;
    const int lane = tid & 31;
    const int h    = blockIdx.x >> 3;
    const int vb   = (blockIdx.x & 7) * 16;       // CTA's 16-column slab
    float* outp = out + h * DKK + vb + warp * 2;  // float2 per (t, warp)

    auto issue = [&](int g) {
#pragma unroll
        for (int s = 0; s < 4; s++) {
            int tu = 4 * g + s;
            float* sp = sm + (tu & 15) * STGF;
            int t = (tu > TT - 1) ? (TT - 1) : tu;
            const float* gp = g_P + ((size_t)t * HH + h) * 512;
            if (tid < 128) cp16(sp + tid * 4, gp + tid * 4);
            if (tid >= 128 && tid < 132)
                cp16(sp + 512 + (tid - 128) * 4,
                     g_BV + ((size_t)t * HH + h) * DKK + vb + (tid - 128) * 4);
            if (tid == 132)
                cp16(sp + 528, g_S4 + ((size_t)t * HH + h) * 4);
        }
        asm volatile("cp.async.commit_group;" ::: "memory");
    };

    issue(0); issue(1); issue(2);

    ull SA0 = 0, SA1 = 0, SB0 = 0, SB1 = 0;
    ull Pq[4] = {0, 0, 0, 0};     // reduced packed P for steps t..t+3
    ull d1 = 0, d2 = 0;           // packed delta_{t-1}, delta_{t-2}

    for (int g = 0; g < TT / 4; g++) {
        // groups g and g+1 complete (w of t+3 lives in group g+1)
        asm volatile("cp.async.wait_group 1;" ::: "memory");
        __syncthreads();
#pragma unroll
        for (int s = 0; s < 4; s++) {
            const int t = 4 * g + s;
            const float* spb = sm + (t & 15) * STGF;
            const int lo = lane * 4;

            // distinct-per-lane array loads (one LDS.128 per array)
            ulonglong2 A = *(const ulonglong2*)(spb + 128 + lo);
            ulonglong2 K = *(const ulonglong2*)(spb + 256 + lo);
            ulonglong2 Q = *(const ulonglong2*)(spb + 384 + lo);
            ulonglong2 W = *(const ulonglong2*)(sm + ((t + 3) & 15) * STGF + lo);

            float4 s4 = *(const float4*)(spb + 528);    // {b, R, Q, -}
            ull R2  = pack2(s4.y);
            ull Q2  = pack2(s4.z);
            ull nB2 = pack2(-s4.x);
            ull BV2 = *(const ull*)(spb + 512 + warp * 2);  // (colA,colB)

            // ---- critical chain: 3 dependent packed FFMA2s ----
            ull r  = ffma2(d2, R2, Pq[s]);
            r      = ffma2(d1, Q2, r);
            ull dt = ffma2(nB2, r, BV2);
            d2 = d1; d1 = dt;
            float dA, dB; unpack2(dA, dB, dt);
            ull DA = pack2(dA), DB = pack2(dB);

            // ---- off-chain: S update + o-dot + P_{t+3}-dot ----
            SA0 = ffma2(A.x, SA0, fmul2(K.x, DA));
            SA1 = ffma2(A.y, SA1, fmul2(K.y, DA));
            SB0 = ffma2(A.x, SB0, fmul2(K.x, DB));
            SB1 = ffma2(A.y, SB1, fmul2(K.y, DB));

            float oA = hsum2(ffma2(Q.x, SA0, fmul2(Q.y, SA1)));
            float oB = hsum2(ffma2(Q.x, SB0, fmul2(Q.y, SB1)));
            float pA = hsum2(ffma2(W.x, SA0, fmul2(W.y, SA1)));
            float pB = hsum2(ffma2(W.x, SB0, fmul2(W.y, SB1)));
            ull ov = packAB(oA, oB);
            ull pv = packAB(pA, pB);

            // 5-level butterfly over all 32 lanes; two interleaved chains
#pragma unroll
            for (int m = 1; m < 32; m <<= 1) {
                ov = fadd2(ov, shfl64(ov, m));
                pv = fadd2(pv, shfl64(pv, m));
            }
            Pq[(s + 3) & 3] = pv;          // P_{t+3} = w_{t+3} . S_t
            if (lane == 0) {
                float xA, xB; unpack2(xA, xB, ov);
                *(float2*)(outp + (size_t)t * (HH * DKK)) =
                    make_float2(xA, xB);
            }
        }
        issue(g + 3);
    }
}

// --------------------------------------------------------------------------
extern "C" void kernel_launch(void* const* d_in, const int* in_sizes, int n_in,
                              void* d_out, int out_size) {
    const float* mixed_qkv   = (const float*)d_in[0];
    const float* forget_gate = (const float*)d_in[1];
    const float* beta        = (const float*)d_in[2];
    const float* conv_w      = (const float*)d_in[3];
    const float* A_log       = (const float*)d_in[4];
    const float* dt_bias     = (const float*)d_in[5];
    float* out = (float*)d_out;

    prep_kernel<<<(TT * HH) / 8, 256>>>(mixed_qkv, forget_gate, beta,
                                        conv_w, A_log, dt_bias);
    pass2_kernel<<<(TT * HH) / 8, 256>>>();
    recur_kernel<<<128, 256>>>(out);
}